// round 4
// baseline (speedup 1.0000x reference)
#include <cuda_runtime.h>
#include <cstdint>

#define Bn 64
#define Nn 50000
#define Ln 8
#define En 100000
#define Un 20000
#define Gn 20000
#define Rn 64
#define Dn 16
#define Cn 2
#define ND (Bn*Dn)   /* 1024 floats per node */

// Scratch (device globals: allocation-free rule)
__device__ float g_h[(size_t)Nn * ND];            // ~204.8 MB  initial values [node][b][d]
__device__ float g_buf[(size_t)Ln * Un * ND];     // ~655 MB    per-layer dst values [l][u][b][d]
__device__ int   g_loc[Nn];                       // node -> (l*Un+u)+1, 0 = still in g_h
__device__ int   g_csr[Ln * En];
__device__ int   g_off[Ln * (Un + 1)];
__device__ int   g_cnt[Ln * Un];
__device__ int   g_cur[Ln * Un];

__global__ void k_zero_h() {
    size_t i = (size_t)blockIdx.x * blockDim.x + threadIdx.x;
    size_t n4 = (size_t)Nn * ND / 4;
    if (i < n4) ((float4*)g_h)[i] = make_float4(0.f, 0.f, 0.f, 0.f);
}

__global__ void k_zero_int() {
    int i = blockIdx.x * blockDim.x + threadIdx.x;
    if (i < Ln * Un) { g_cnt[i] = 0; g_cur[i] = 0; }
    if (i < Nn) g_loc[i] = 0;
}

// h[gene_map[g]] = X[b,g] * w_in + b_in  (block = gene, thread = (b, j0))
__global__ void k_gene(const float* __restrict__ X, const float* __restrict__ w_in,
                       const float* __restrict__ b_in, const int* __restrict__ gene_map) {
    int g = blockIdx.x;
    int t = threadIdx.x;
    int b = t >> 2, j0 = (t & 3) << 2;
    int node = gene_map[g];
    float x = X[(size_t)b * Gn + g];
    float4 w  = *(const float4*)(w_in + j0);
    float4 bi = *(const float4*)(b_in + j0);
    float4 v = make_float4(fmaf(x, w.x, bi.x), fmaf(x, w.y, bi.y),
                           fmaf(x, w.z, bi.z), fmaf(x, w.w, bi.w));
    *(float4*)(g_h + (size_t)node * ND + t * 4) = v;
}

__global__ void k_hist(const int* __restrict__ dst_pos) {
    int i = blockIdx.x * blockDim.x + threadIdx.x;
    if (i < Ln * En) {
        int l = i / En;
        atomicAdd(&g_cnt[l * Un + dst_pos[i]], 1);
    }
}

// Exclusive scan of counts -> offsets, one block per layer.
__global__ void k_scan() {
    int l = blockIdx.x;
    const int* c = g_cnt + l * Un;
    int* o = g_off + l * (Un + 1);
    __shared__ int sh[1024];
    __shared__ int sbase;
    if (threadIdx.x == 0) sbase = 0;
    __syncthreads();
    for (int start = 0; start < Un; start += 1024) {
        int idx = start + (int)threadIdx.x;
        int v = (idx < Un) ? c[idx] : 0;
        sh[threadIdx.x] = v;
        __syncthreads();
        for (int st = 1; st < 1024; st <<= 1) {
            int tv = (threadIdx.x >= (unsigned)st) ? sh[threadIdx.x - st] : 0;
            __syncthreads();
            sh[threadIdx.x] += tv;
            __syncthreads();
        }
        if (idx < Un) o[idx] = sbase + sh[threadIdx.x] - v;  // exclusive
        __syncthreads();
        if (threadIdx.x == 0) sbase += sh[1023];
        __syncthreads();
    }
    if (threadIdx.x == 0) o[Un] = sbase;
}

__global__ void k_fill(const int* __restrict__ dst_pos) {
    int i = blockIdx.x * blockDim.x + threadIdx.x;
    if (i < Ln * En) {
        int l = i / En;
        int e = i - l * En;
        int u = dst_pos[i];
        int slot = g_off[l * (Un + 1) + u] + atomicAdd(&g_cur[l * Un + u], 1);
        g_csr[l * En + slot] = e;
    }
}

// Sort each bucket by edge id (deterministic sum order), then map edge id -> src node id.
__global__ void k_sortconv(const int* __restrict__ src) {
    int gid = blockIdx.x * blockDim.x + threadIdx.x;
    if (gid >= Ln * Un) return;
    int l = gid / Un;
    int u = gid - l * Un;
    int* seg = g_csr + l * En;
    int lo = g_off[l * (Un + 1) + u];
    int hi = g_off[l * (Un + 1) + u + 1];
    for (int i = lo + 1; i < hi; i++) {
        int key = seg[i];
        int j = i - 1;
        while (j >= lo && seg[j] > key) { seg[j + 1] = seg[j]; j--; }
        seg[j + 1] = key;
    }
    const int* sl = src + l * En;
    for (int i = lo; i < hi; i++) seg[i] = sl[seg[i]];
}

// One block per dst slot u. Thread = (b = t>>2, q = t&3).
// Phase 1: S[b][k] = sum_edges val(src)[b][k] for k in q-slice (1 LDG.128/edge/thread)
// Phase 2: partial_j = sum_{k in slice} S[k] * W[k][j]  for ALL j (32 FFMA2)
// Phase 3: smem reduce over q, add bias, tanh, write g_buf[l][u].
__global__ __launch_bounds__(256) void k_gather(int l, const float* __restrict__ W,
                                                const float* __restrict__ bias,
                                                const int* __restrict__ dstu) {
    int u = blockIdx.x;
    int t = threadIdx.x;
    int b = t >> 2, q = t & 3;

    const int* off = g_off + l * (Un + 1);
    int lo = off[u], hi = off[u + 1];
    int n = hi - lo;
    const int* e = g_csr + l * En + lo;

    // Phase 1: sum of source values over edges, this thread's 4 k-dims.
    float a0 = 0.f, a1 = 0.f, a2 = 0.f, a3 = 0.f;
    #pragma unroll
    for (int i = 0; i < 8; i++) {
        if (i < n) {
            int s = e[i];
            int v = g_loc[s];
            const float* base = v ? (g_buf + (size_t)(v - 1) * ND)
                                  : (g_h + (size_t)s * ND);
            float4 d = *(const float4*)(base + (t << 2));
            a0 += d.x; a1 += d.y; a2 += d.z; a3 += d.w;
        }
    }
    for (int i = 8; i < n; i++) {
        int s = e[i];
        int v = g_loc[s];
        const float* base = v ? (g_buf + (size_t)(v - 1) * ND)
                              : (g_h + (size_t)s * ND);
        float4 d = *(const float4*)(base + (t << 2));
        a0 += d.x; a1 += d.y; a2 += d.z; a3 += d.w;
    }
    float sv[4] = { a0, a1, a2, a3 };

    // Phase 2: partial transform over this thread's k-slice, all 16 outputs.
    unsigned long long acc[8];
    #pragma unroll
    for (int jp = 0; jp < 8; jp++) acc[jp] = 0ull;
    const float* Wl = W + l * Dn * Dn;
    #pragma unroll
    for (int kk = 0; kk < 4; kk++) {
        int row = (q << 2) + kk;
        ulonglong2 wa = *(const ulonglong2*)(Wl + row * Dn);
        ulonglong2 wb = *(const ulonglong2*)(Wl + row * Dn + 4);
        ulonglong2 wc = *(const ulonglong2*)(Wl + row * Dn + 8);
        ulonglong2 wd = *(const ulonglong2*)(Wl + row * Dn + 12);
        unsigned long long s2;
        asm("mov.b64 %0, {%1, %1};" : "=l"(s2) : "f"(sv[kk]));
        asm("fma.rn.f32x2 %0, %1, %2, %0;" : "+l"(acc[0]) : "l"(s2), "l"(wa.x));
        asm("fma.rn.f32x2 %0, %1, %2, %0;" : "+l"(acc[1]) : "l"(s2), "l"(wa.y));
        asm("fma.rn.f32x2 %0, %1, %2, %0;" : "+l"(acc[2]) : "l"(s2), "l"(wb.x));
        asm("fma.rn.f32x2 %0, %1, %2, %0;" : "+l"(acc[3]) : "l"(s2), "l"(wb.y));
        asm("fma.rn.f32x2 %0, %1, %2, %0;" : "+l"(acc[4]) : "l"(s2), "l"(wc.x));
        asm("fma.rn.f32x2 %0, %1, %2, %0;" : "+l"(acc[5]) : "l"(s2), "l"(wc.y));
        asm("fma.rn.f32x2 %0, %1, %2, %0;" : "+l"(acc[6]) : "l"(s2), "l"(wd.x));
        asm("fma.rn.f32x2 %0, %1, %2, %0;" : "+l"(acc[7]) : "l"(s2), "l"(wd.y));
    }

    // Phase 3: reduce partials over q via smem, then bias + tanh + store.
    __shared__ float sred[4 * 1028];
    float* myrow = sred + q * 1028 + (b << 4);
    #pragma unroll
    for (int jp = 0; jp < 8; jp++) {
        float flo, fhi;
        asm("mov.b64 {%0, %1}, %2;" : "=f"(flo), "=f"(fhi) : "l"(acc[jp]));
        ((float2*)myrow)[jp] = make_float2(flo, fhi);
    }
    __syncthreads();

    float4 r = make_float4(0.f, 0.f, 0.f, 0.f);
    #pragma unroll
    for (int qq = 0; qq < 4; qq++) {
        float4 p = *(const float4*)(sred + qq * 1028 + (b << 4) + (q << 2));
        r.x += p.x; r.y += p.y; r.z += p.z; r.w += p.w;
    }

    int node = dstu[u];
    float4 bi = *(const float4*)(bias + (size_t)node * Dn + (q << 2));
    float4 outv = make_float4(tanhf(r.x + bi.x), tanhf(r.y + bi.y),
                              tanhf(r.z + bi.z), tanhf(r.w + bi.w));
    *(float4*)(g_buf + ((size_t)l * Un + u) * ND + (t << 2)) = outv;
}

// After layer l's gather: record that dst nodes now live in g_buf[l][u].
__global__ void k_loc(int l, const int* __restrict__ dstu) {
    int u = blockIdx.x * blockDim.x + threadIdx.x;
    if (u < Un) g_loc[dstu[u]] = l * Un + u + 1;
}

// out[b,c] = sum_{r,j} val(root[r])[b][j] * W_head[c][r*16+j] + b_head[c]
__global__ void k_head(const int* __restrict__ roots, const float* __restrict__ Wh,
                       const float* __restrict__ bh, float* __restrict__ out) {
    int b = blockIdx.x;
    int t = threadIdx.x;
    float a0 = 0.f, a1 = 0.f;
    for (int i = t; i < Rn * Dn; i += 256) {
        int r = i >> 4, j = i & 15;
        int node = roots[r];
        int v = g_loc[node];
        const float* base = v ? (g_buf + (size_t)(v - 1) * ND)
                              : (g_h + (size_t)node * ND);
        float f = base[(b << 4) + j];
        a0 = fmaf(f, Wh[i], a0);
        a1 = fmaf(f, Wh[Rn * Dn + i], a1);
    }
    __shared__ float s0[256], s1[256];
    s0[t] = a0; s1[t] = a1;
    __syncthreads();
    for (int st = 128; st > 0; st >>= 1) {
        if (t < st) { s0[t] += s0[t + st]; s1[t] += s1[t + st]; }
        __syncthreads();
    }
    if (t == 0) {
        out[b * Cn + 0] = s0[0] + bh[0];
        out[b * Cn + 1] = s1[0] + bh[1];
    }
}

extern "C" void kernel_launch(void* const* d_in, const int* in_sizes, int n_in,
                              void* d_out, int out_size) {
    (void)in_sizes; (void)n_in; (void)out_size;
    const float* X          = (const float*)d_in[0];
    const float* w_in       = (const float*)d_in[1];
    const float* b_in       = (const float*)d_in[2];
    const float* W          = (const float*)d_in[3];
    const float* bias       = (const float*)d_in[4];
    const float* W_head     = (const float*)d_in[5];
    const float* b_head     = (const float*)d_in[6];
    const int*   gene_map   = (const int*)d_in[7];
    const int*   src        = (const int*)d_in[8];
    const int*   dst_pos    = (const int*)d_in[9];
    const int*   dst_unique = (const int*)d_in[10];
    const int*   root_ids   = (const int*)d_in[11];
    float* out = (float*)d_out;

    {
        size_t n4 = (size_t)Nn * ND / 4;
        k_zero_h<<<(unsigned)((n4 + 255) / 256), 256>>>();
    }
    k_zero_int<<<(Ln * Un + 255) / 256, 256>>>();
    k_gene<<<Gn, 256>>>(X, w_in, b_in, gene_map);

    // Batched CSR build for all 8 layers (depends only on dst_pos / src)
    k_hist<<<(Ln * En + 255) / 256, 256>>>(dst_pos);
    k_scan<<<Ln, 1024>>>();
    k_fill<<<(Ln * En + 255) / 256, 256>>>(dst_pos);
    k_sortconv<<<(Ln * Un + 255) / 256, 256>>>(src);

    for (int l = 0; l < Ln; l++) {
        k_gather<<<Un, 256>>>(l, W, bias, dst_unique + l * Un);
        k_loc<<<(Un + 255) / 256, 256>>>(l, dst_unique + l * Un);
    }

    k_head<<<Bn, 256>>>(root_ids, W_head, b_head, out);
}